// round 9
// baseline (speedup 1.0000x reference)
#include <cuda_runtime.h>
#include <cuda_bf16.h>
#include <cstdint>

#define HDIM 1024
#define BDIM 2048
#define SDIM 64
#define MROWS (BDIM * SDIM)   // 131072

// ---------------- scratch ----------------
__device__ __nv_bfloat16 g_abf [(size_t)MROWS * HDIM];   // prev_out_M bf16
__device__ __nv_bfloat16 g_inbf[(size_t)BDIM * HDIM];    // in_val bf16
__device__ __nv_bfloat16 g_wqt [(size_t)HDIM * HDIM];    // Wq^T bf16
__device__ __nv_bfloat16 g_wkt [(size_t)HDIM * HDIM];    // Wk^T bf16
__device__ __nv_bfloat16 g_kc  [(size_t)MROWS * HDIM];
__device__ __nv_bfloat16 g_qpre[(size_t)BDIM * HDIM];
__device__ float         g_q   [(size_t)BDIM * HDIM];
__device__ float         g_beta[(size_t)BDIM * SDIM];

#define CPASYNC16(sm, gm) \
    asm volatile("cp.async.cg.shared.global [%0], [%1], 16;\n" :: "r"(sm), "l"(gm))
#define CP_COMMIT() asm volatile("cp.async.commit_group;\n" ::: "memory")
#define CP_WAIT1()  asm volatile("cp.async.wait_group 1;\n" ::: "memory")
#define CP_WAIT0()  asm volatile("cp.async.wait_group 0;\n" ::: "memory")
#define LDMX4(r0, r1, r2, r3, a) \
    asm volatile("ldmatrix.sync.aligned.m8n8.x4.shared.b16 {%0,%1,%2,%3}, [%4];" \
        : "=r"(r0), "=r"(r1), "=r"(r2), "=r"(r3) : "r"(a))

__device__ __forceinline__ uint32_t smem_u32(const void* p) {
    uint32_t a;
    asm("{ .reg .u64 t; cvta.to.shared.u64 t, %1; cvt.u32.u64 %0, t; }" : "=r"(a) : "l"(p));
    return a;
}

// ================= pipelined bf16 mma.sync GEMM =================
// C[M,1024] = A[M,1024] @ Bt^T  (A, Bt bf16; Bt n-major).
// CTA tile 128x128, 4 warps (2x2), warp tile 64x64, k-chunk 64,
// 3-stage cp.async ring, 1 barrier/chunk, 2 CTAs/SM.
#define NSTG   3
#define KC     64
#define CHUNKS (HDIM / KC)              // 16
#define RSTRIDE 144                     // bytes/row: 64 bf16 + 8 pad
#define STG_A   (128 * RSTRIDE)         // 18432 B
#define STG_BYTES (2 * STG_A)           // 36864 B
#define GEMM_SMEM (NSTG * STG_BYTES)    // 110592 B

__global__ __launch_bounds__(128, 2) void gemm_bf16_k(
    const __nv_bfloat16* __restrict__ A, const __nv_bfloat16* __restrict__ Bt,
    __nv_bfloat16* __restrict__ C)
{
    extern __shared__ __align__(128) char smem[];
    const uint32_t sb = smem_u32(smem);

    const int tid   = threadIdx.x;
    const int lane  = tid & 31;
    const int wid   = tid >> 5;
    const int warpM = wid >> 1;      // 0..1
    const int warpN = wid & 1;       // 0..1
    const size_t bm = (size_t)blockIdx.y * 128;
    const size_t bn = (size_t)blockIdx.x * 128;

    float acc[4][8][4];
    #pragma unroll
    for (int mt = 0; mt < 4; mt++)
        #pragma unroll
        for (int nt = 0; nt < 8; nt++)
            #pragma unroll
            for (int i = 0; i < 4; i++) acc[mt][nt][i] = 0.f;

    // producer mapping: 128 threads, each copies one full 128B row of A and of B
    const __nv_bfloat16* gA = A  + (bm + tid) * HDIM;
    const __nv_bfloat16* gB = Bt + (bn + tid) * HDIM;
    const uint32_t pdst = tid * RSTRIDE;

    // ldmatrix base offsets within a stage
    const uint32_t aF = (warpM * 64 + ((lane >> 3) & 1) * 8 + (lane & 7)) * RSTRIDE
                      + (lane >> 4) * 16;
    const uint32_t bF = STG_A
                      + (warpN * 64 + ((lane >> 4) & 1) * 8 + (lane & 7)) * RSTRIDE
                      + ((lane >> 3) & 1) * 16;

    // prologue: chunks 0,1
    #pragma unroll
    for (int kt = 0; kt < 2; kt++) {
        const uint32_t s = sb + kt * STG_BYTES;
        #pragma unroll
        for (int g = 0; g < 8; g++) {
            CPASYNC16(s + pdst + g * 16,         gA + kt * KC + g * 8);
            CPASYNC16(s + STG_A + pdst + g * 16, gB + kt * KC + g * 8);
        }
        CP_COMMIT();
    }

    for (int kt = 0; kt < CHUNKS; kt++) {
        if (kt < CHUNKS - 1) CP_WAIT1(); else CP_WAIT0();
        __syncthreads();   // chunk kt visible; slot (kt+2)%3 free

        if (kt + 2 < CHUNKS) {
            const uint32_t s = sb + ((kt + 2) % NSTG) * STG_BYTES;
            #pragma unroll
            for (int g = 0; g < 8; g++) {
                CPASYNC16(s + pdst + g * 16,         gA + (kt + 2) * KC + g * 8);
                CPASYNC16(s + STG_A + pdst + g * 16, gB + (kt + 2) * KC + g * 8);
            }
            CP_COMMIT();
        }

        const uint32_t stg = sb + (kt % NSTG) * STG_BYTES;
        #pragma unroll
        for (int ks = 0; ks < KC; ks += 16) {
            uint32_t af[4][4];
            uint32_t bf[8][2];
            #pragma unroll
            for (int mt = 0; mt < 4; mt++)
                LDMX4(af[mt][0], af[mt][1], af[mt][2], af[mt][3],
                      stg + aF + mt * 16 * RSTRIDE + ks * 2);
            #pragma unroll
            for (int np = 0; np < 4; np++) {
                uint32_t b0, b1, b2, b3;
                LDMX4(b0, b1, b2, b3, stg + bF + np * 16 * RSTRIDE + ks * 2);
                bf[2*np][0]   = b0; bf[2*np][1]   = b1;
                bf[2*np+1][0] = b2; bf[2*np+1][1] = b3;
            }
            #pragma unroll
            for (int mt = 0; mt < 4; mt++)
                #pragma unroll
                for (int nt = 0; nt < 8; nt++)
                    asm volatile(
                        "mma.sync.aligned.m16n8k16.row.col.f32.bf16.bf16.f32 "
                        "{%0,%1,%2,%3},{%4,%5,%6,%7},{%8,%9},{%0,%1,%2,%3};\n"
                        : "+f"(acc[mt][nt][0]), "+f"(acc[mt][nt][1]),
                          "+f"(acc[mt][nt][2]), "+f"(acc[mt][nt][3])
                        : "r"(af[mt][0]), "r"(af[mt][1]), "r"(af[mt][2]), "r"(af[mt][3]),
                          "r"(bf[nt][0]), "r"(bf[nt][1]));
        }
    }

    #pragma unroll
    for (int mt = 0; mt < 4; mt++) {
        int r = warpM * 64 + mt * 16 + (lane >> 2);
        #pragma unroll
        for (int nt = 0; nt < 8; nt++) {
            size_t c  = bn + warpN * 64 + nt * 8 + (lane & 3) * 2;
            size_t b0 = (bm + r) * HDIM + c;
            *(__nv_bfloat162*)(C + b0) =
                __floats2bfloat162_rn(acc[mt][nt][0], acc[mt][nt][1]);
            *(__nv_bfloat162*)(C + b0 + (size_t)8 * HDIM) =
                __floats2bfloat162_rn(acc[mt][nt][2], acc[mt][nt][3]);
        }
    }
}

// ---------------- fp32 -> bf16 convert ----------------
__global__ __launch_bounds__(256) void cvt_k(const float* __restrict__ in,
                                             __nv_bfloat16* __restrict__ out)
{
    size_t i = ((size_t)blockIdx.x * blockDim.x + threadIdx.x) * 8;
    float4 a = *(const float4*)(in + i);
    float4 b = *(const float4*)(in + i + 4);
    __nv_bfloat162 r[4];
    r[0] = __floats2bfloat162_rn(a.x, a.y);
    r[1] = __floats2bfloat162_rn(a.z, a.w);
    r[2] = __floats2bfloat162_rn(b.x, b.y);
    r[3] = __floats2bfloat162_rn(b.z, b.w);
    *(uint4*)(out + i) = *(const uint4*)r;
}

// ---------------- transpose + convert ----------------
__global__ __launch_bounds__(256) void cvtT_k(const float* __restrict__ W,
                                              __nv_bfloat16* __restrict__ Wt)
{
    __shared__ float t[32][33];
    int x  = blockIdx.x * 32 + threadIdx.x;
    int y0 = blockIdx.y * 32;
    #pragma unroll
    for (int r = threadIdx.y; r < 32; r += 8)
        t[r][threadIdx.x] = W[(size_t)(y0 + r) * HDIM + x];
    __syncthreads();
    int xo = y0 + threadIdx.x;
    #pragma unroll
    for (int r = threadIdx.y; r < 32; r += 8)
        Wt[(size_t)(blockIdx.x * 32 + r) * HDIM + xo] = __float2bfloat16(t[threadIdx.x][r]);
}

// ---------------- LayerNorm for query ----------------
__global__ __launch_bounds__(256) void ln_q_k(
    const __nv_bfloat16* __restrict__ qpre,
    const float* __restrict__ bq, const float* __restrict__ gq,
    const float* __restrict__ betaq, float* __restrict__ qout)
{
    const int lane = threadIdx.x & 31;
    const int wid  = threadIdx.x >> 5;
    const int row  = blockIdx.x * 8 + wid;
    const size_t base = (size_t)row * HDIM;

    float x[32];
    float s = 0.f, sq = 0.f;
    #pragma unroll
    for (int i = 0; i < 16; i++) {
        int j = i * 64 + lane * 2;
        __nv_bfloat162 v = *(const __nv_bfloat162*)(qpre + base + j);
        float a = __low2float(v)  + bq[j];
        float c = __high2float(v) + bq[j + 1];
        x[2*i] = a; x[2*i+1] = c;
        s += a + c; sq += a * a + c * c;
    }
    #pragma unroll
    for (int o = 16; o > 0; o >>= 1) {
        s  += __shfl_xor_sync(0xffffffffu, s,  o);
        sq += __shfl_xor_sync(0xffffffffu, sq, o);
    }
    float mean = s * (1.f / 1024.f);
    float var  = sq * (1.f / 1024.f) - mean * mean;
    float rstd = rsqrtf(var + 1e-5f);
    #pragma unroll
    for (int i = 0; i < 16; i++) {
        int j = i * 64 + lane * 2;
        float2 o;
        o.x = (x[2*i]   - mean) * rstd * gq[j]   + betaq[j];
        o.y = (x[2*i+1] - mean) * rstd * gq[j+1] + betaq[j+1];
        *(float2*)(qout + base + j) = o;
    }
}

// ---------------- fused: keyp-LN + relu(q+keyp) . Wb -> beta ----------------
__global__ __launch_bounds__(256) void beta_k(
    const __nv_bfloat16* __restrict__ kc, const float* __restrict__ q,
    const float* __restrict__ bk, const float* __restrict__ gk,
    const float* __restrict__ betak, const float* __restrict__ Wb,
    const float* __restrict__ bb, float* __restrict__ beta)
{
    __shared__ float bks[HDIM], gks[HDIM], cqs[HDIM], wbs[HDIM];
    const int b    = blockIdx.x;
    const int tid  = threadIdx.x;
    const int lane = tid & 31;
    const int wid  = tid >> 5;

    for (int j = tid; j < HDIM; j += 256) {
        bks[j] = bk[j];
        gks[j] = gk[j];
        cqs[j] = betak[j] + q[(size_t)b * HDIM + j];
        wbs[j] = Wb[j];
    }
    __syncthreads();
    const float bbv = bb[0];

    for (int s = wid; s < SDIM; s += 8) {
        const size_t base = ((size_t)b * SDIM + s) * HDIM;
        float x[32];
        float sm = 0.f, sq = 0.f;
        #pragma unroll
        for (int it = 0; it < 4; it++) {
            int j0 = it * 256 + lane * 8;
            uint4 raw = *(const uint4*)(kc + base + j0);
            const __nv_bfloat162* v2 = (const __nv_bfloat162*)&raw;
            #pragma unroll
            for (int e = 0; e < 4; e++) {
                float a = __low2float(v2[e])  + bks[j0 + 2*e];
                float c = __high2float(v2[e]) + bks[j0 + 2*e + 1];
                x[it*8 + 2*e]     = a;
                x[it*8 + 2*e + 1] = c;
                sm += a + c; sq += a * a + c * c;
            }
        }
        #pragma unroll
        for (int o = 16; o > 0; o >>= 1) {
            sm += __shfl_xor_sync(0xffffffffu, sm, o);
            sq += __shfl_xor_sync(0xffffffffu, sq, o);
        }
        float mean = sm * (1.f / 1024.f);
        float var  = sq * (1.f / 1024.f) - mean * mean;
        float rstd = rsqrtf(var + 1e-5f);

        float acc = 0.f;
        #pragma unroll
        for (int it = 0; it < 4; it++) {
            int j0 = it * 256 + lane * 8;
            #pragma unroll
            for (int e = 0; e < 8; e++) {
                float hv = (x[it*8 + e] - mean) * rstd * gks[j0 + e] + cqs[j0 + e];
                acc += fmaxf(hv, 0.f) * wbs[j0 + e];
            }
        }
        #pragma unroll
        for (int o = 16; o > 0; o >>= 1)
            acc += __shfl_xor_sync(0xffffffffu, acc, o);

        if (lane == 0)
            beta[(size_t)b * SDIM + s] = (acc + bbv) * (1.f / 32.f);
    }
}

// ---------------- masked softmax + cumsums ----------------
__global__ void softmax_k(const float* __restrict__ beta,
                          const float* __restrict__ prev_p,
                          float* __restrict__ out)
{
    int b = blockIdx.x * blockDim.x + threadIdx.x;
    if (b >= BDIM) return;
    const float* bt = beta   + (size_t)b * SDIM;
    const float* pp = prev_p + (size_t)b * SDIM;

    float mx = -1e30f;
    #pragma unroll
    for (int s = 0; s < SDIM; s++) mx = fmaxf(mx, bt[s]);

    float pcs[SDIM];
    float run = 0.f;
    #pragma unroll
    for (int s = 0; s < SDIM; s++) { run += pp[s]; pcs[s] = run; }

    float x[SDIM];
    float denom = 0.f;
    #pragma unroll
    for (int s = 0; s < SDIM; s++) {
        float mask = (s < SDIM - 1)
                   ? ((pcs[s + 1] < 1e-5f) ? 0.f : pcs[s + 1])
                   : 1.f;
        x[s] = expf(bt[s] - mx) * mask;
        denom += fabsf(x[s]);
    }
    denom = fmaxf(denom, 1e-12f);

    const size_t BS = (size_t)BDIM * SDIM;
    float cp = 0.f;
    #pragma unroll
    for (int s = 0; s < SDIM; s++) {
        float p = x[s] / denom;
        x[s] = p;
        cp += p;
        out[0 * BS + (size_t)b * SDIM + s] = cp;
        out[2 * BS + (size_t)b * SDIM + s] = p;
    }
    float rcp = 0.f;
    #pragma unroll
    for (int s = SDIM - 1; s >= 0; s--) {
        rcp += x[s];
        out[1 * BS + (size_t)b * SDIM + s] = rcp;
    }
}

// ---------------- launch ----------------
extern "C" void kernel_launch(void* const* d_in, const int* in_sizes, int n_in,
                              void* d_out, int out_size)
{
    const float* in_val     = (const float*)d_in[0];
    const float* prev_out_M = (const float*)d_in[1];
    const float* prev_p     = (const float*)d_in[2];
    const float* Wq         = (const float*)d_in[3];
    const float* bq         = (const float*)d_in[4];
    const float* gq         = (const float*)d_in[5];
    const float* betaq      = (const float*)d_in[6];
    const float* Wk         = (const float*)d_in[7];
    const float* bk         = (const float*)d_in[8];
    const float* gk         = (const float*)d_in[9];
    const float* betak      = (const float*)d_in[10];
    const float* Wb         = (const float*)d_in[11];
    const float* bb         = (const float*)d_in[12];
    float* out = (float*)d_out;

    __nv_bfloat16 *abf, *inbf, *wqt, *wkt, *kc, *qpre;
    float *qf, *betap;
    cudaGetSymbolAddress((void**)&abf,   g_abf);
    cudaGetSymbolAddress((void**)&inbf,  g_inbf);
    cudaGetSymbolAddress((void**)&wqt,   g_wqt);
    cudaGetSymbolAddress((void**)&wkt,   g_wkt);
    cudaGetSymbolAddress((void**)&kc,    g_kc);
    cudaGetSymbolAddress((void**)&qpre,  g_qpre);
    cudaGetSymbolAddress((void**)&qf,    g_q);
    cudaGetSymbolAddress((void**)&betap, g_beta);

    cudaFuncSetAttribute(gemm_bf16_k, cudaFuncAttributeMaxDynamicSharedMemorySize, GEMM_SMEM);

    cvt_k <<<((size_t)MROWS * HDIM / 8) / 256, 256>>>(prev_out_M, abf);
    cvt_k <<<((size_t)BDIM  * HDIM / 8) / 256, 256>>>(in_val, inbf);
    cvtT_k<<<dim3(32, 32), dim3(32, 8)>>>(Wq, wqt);
    cvtT_k<<<dim3(32, 32), dim3(32, 8)>>>(Wk, wkt);

    gemm_bf16_k<<<dim3(8, BDIM  / 128), 128, GEMM_SMEM>>>(inbf, wqt, qpre);
    gemm_bf16_k<<<dim3(8, MROWS / 128), 128, GEMM_SMEM>>>(abf,  wkt, kc);

    ln_q_k   <<<BDIM / 8, 256>>>(qpre, bq, gq, betaq, qf);
    beta_k   <<<BDIM, 256>>>(kc, qf, bk, gk, betak, Wb, bb, betap);
    softmax_k<<<(BDIM + 127) / 128, 128>>>(betap, prev_p, out);
}

// round 10
// speedup vs baseline: 1.5104x; 1.5104x over previous
#include <cuda_runtime.h>
#include <cuda_bf16.h>
#include <cstdint>

#define HDIM 1024
#define BDIM 2048
#define SDIM 64
#define MROWS (BDIM * SDIM)   // 131072

// ---------------- scratch ----------------
__device__ __nv_bfloat16 g_abf [(size_t)MROWS * HDIM];
__device__ __nv_bfloat16 g_inbf[(size_t)BDIM * HDIM];
__device__ __nv_bfloat16 g_wqt [(size_t)HDIM * HDIM];
__device__ __nv_bfloat16 g_wkt [(size_t)HDIM * HDIM];
__device__ __nv_bfloat16 g_kc  [(size_t)MROWS * HDIM];
__device__ __nv_bfloat16 g_qpre[(size_t)BDIM * HDIM];
__device__ float         g_q   [(size_t)BDIM * HDIM];
__device__ float         g_beta[(size_t)BDIM * SDIM];

#define CPASYNC16(sm, gm) \
    asm volatile("cp.async.cg.shared.global [%0], [%1], 16;\n" :: "r"(sm), "l"(gm))
#define CP_COMMIT() asm volatile("cp.async.commit_group;\n" ::: "memory")
#define CP_WAIT1()  asm volatile("cp.async.wait_group 1;\n" ::: "memory")
#define CP_WAIT0()  asm volatile("cp.async.wait_group 0;\n" ::: "memory")
#define LDMX4(r0, r1, r2, r3, a) \
    asm volatile("ldmatrix.sync.aligned.m8n8.x4.shared.b16 {%0,%1,%2,%3}, [%4];" \
        : "=r"(r0), "=r"(r1), "=r"(r2), "=r"(r3) : "r"(a))

__device__ __forceinline__ uint32_t smem_u32(const void* p) {
    uint32_t a;
    asm("{ .reg .u64 t; cvta.to.shared.u64 t, %1; cvt.u32.u64 %0, t; }" : "=r"(a) : "l"(p));
    return a;
}

// ================= pipelined bf16 mma.sync GEMM (exact R4 config) =================
// C[M,1024] = A[M,1024] @ Bt^T  (Bt n-major). CTA tile 128x128, k-chunk 64,
// 3-stage cp.async ring, 1 syncthreads/chunk, ldmatrix fragment loads,
// 2 CTAs/SM. 8 warps (2x4), warp tile 64x32.
#define NSTG   3
#define KC     64
#define CHUNKS (HDIM / KC)              // 16
#define RSTRIDE 144                     // bytes per smem row (64 bf16 + 8 pad)
#define STG_A   (128 * RSTRIDE)         // 18432 B
#define STG_BYTES (2 * STG_A)           // 36864 B (A + B)
#define GEMM_SMEM (NSTG * STG_BYTES)    // 110592 B

__global__ __launch_bounds__(256, 2) void gemm_bf16_k(
    const __nv_bfloat16* __restrict__ A, const __nv_bfloat16* __restrict__ Bt,
    __nv_bfloat16* __restrict__ C)
{
    extern __shared__ __align__(128) char smem[];
    const uint32_t sb = smem_u32(smem);

    const int tid   = threadIdx.x;
    const int lane  = tid & 31;
    const int wid   = tid >> 5;
    const int warpM = wid >> 2;      // 0..1
    const int warpN = wid & 3;       // 0..3
    const size_t bm = (size_t)blockIdx.y * 128;
    const size_t bn = (size_t)blockIdx.x * 128;

    float acc[4][4][4];
    #pragma unroll
    for (int mt = 0; mt < 4; mt++)
        #pragma unroll
        for (int nt = 0; nt < 4; nt++)
            #pragma unroll
            for (int i = 0; i < 4; i++) acc[mt][nt][i] = 0.f;

    // producer mapping: 256 threads x 4 iters x 16B per matrix
    const int prow = tid >> 3;          // 0..31 (+ i*32)
    const int pg   = tid & 7;           // 16B granule in row
    const __nv_bfloat16* gA = A  + (bm + prow) * HDIM + pg * 8;
    const __nv_bfloat16* gB = Bt + (bn + prow) * HDIM + pg * 8;
    const uint32_t pdst = prow * RSTRIDE + pg * 16;

    // ldmatrix base offsets (within a stage)
    const uint32_t aF = (warpM * 64 + ((lane >> 3) & 1) * 8 + (lane & 7)) * RSTRIDE
                      + ((lane >> 4) * 8) * 2;
    const uint32_t bF = STG_A
                      + (warpN * 32 + ((lane >> 4) & 1) * 8 + (lane & 7)) * RSTRIDE
                      + (((lane >> 3) & 1) * 8) * 2;

    // prologue: chunks 0,1
    #pragma unroll
    for (int kt = 0; kt < 2; kt++) {
        const uint32_t s = sb + kt * STG_BYTES;
        #pragma unroll
        for (int i = 0; i < 4; i++) {
            CPASYNC16(s + pdst + i * 32 * RSTRIDE,          gA + (size_t)i * 32 * HDIM + kt * KC);
            CPASYNC16(s + STG_A + pdst + i * 32 * RSTRIDE,  gB + (size_t)i * 32 * HDIM + kt * KC);
        }
        CP_COMMIT();
    }

    for (int kt = 0; kt < CHUNKS; kt++) {
        if (kt < CHUNKS - 1) CP_WAIT1(); else CP_WAIT0();
        __syncthreads();   // chunk kt visible; all warps done with buf (kt+2)%3

        if (kt + 2 < CHUNKS) {
            const uint32_t s = sb + ((kt + 2) % NSTG) * STG_BYTES;
            #pragma unroll
            for (int i = 0; i < 4; i++) {
                CPASYNC16(s + pdst + i * 32 * RSTRIDE,         gA + (size_t)i * 32 * HDIM + (kt + 2) * KC);
                CPASYNC16(s + STG_A + pdst + i * 32 * RSTRIDE, gB + (size_t)i * 32 * HDIM + (kt + 2) * KC);
            }
            CP_COMMIT();
        }

        const uint32_t stg = sb + (kt % NSTG) * STG_BYTES;
        #pragma unroll
        for (int ks = 0; ks < KC; ks += 16) {
            uint32_t af[4][4];
            uint32_t bf[4][2];
            #pragma unroll
            for (int mt = 0; mt < 4; mt++)
                LDMX4(af[mt][0], af[mt][1], af[mt][2], af[mt][3],
                      stg + aF + mt * 16 * RSTRIDE + ks * 2);
            #pragma unroll
            for (int np = 0; np < 2; np++) {
                uint32_t b0, b1, b2, b3;
                LDMX4(b0, b1, b2, b3, stg + bF + np * 16 * RSTRIDE + ks * 2);
                bf[2*np][0]   = b0; bf[2*np][1]   = b1;
                bf[2*np+1][0] = b2; bf[2*np+1][1] = b3;
            }
            #pragma unroll
            for (int mt = 0; mt < 4; mt++)
                #pragma unroll
                for (int nt = 0; nt < 4; nt++)
                    asm volatile(
                        "mma.sync.aligned.m16n8k16.row.col.f32.bf16.bf16.f32 "
                        "{%0,%1,%2,%3},{%4,%5,%6,%7},{%8,%9},{%0,%1,%2,%3};\n"
                        : "+f"(acc[mt][nt][0]), "+f"(acc[mt][nt][1]),
                          "+f"(acc[mt][nt][2]), "+f"(acc[mt][nt][3])
                        : "r"(af[mt][0]), "r"(af[mt][1]), "r"(af[mt][2]), "r"(af[mt][3]),
                          "r"(bf[nt][0]), "r"(bf[nt][1]));
        }
    }

    #pragma unroll
    for (int mt = 0; mt < 4; mt++) {
        int r = warpM * 64 + mt * 16 + (lane >> 2);
        #pragma unroll
        for (int nt = 0; nt < 4; nt++) {
            size_t c  = bn + warpN * 32 + nt * 8 + (lane & 3) * 2;
            size_t b0 = (bm + r) * HDIM + c;
            *(__nv_bfloat162*)(C + b0) =
                __floats2bfloat162_rn(acc[mt][nt][0], acc[mt][nt][1]);
            *(__nv_bfloat162*)(C + b0 + (size_t)8 * HDIM) =
                __floats2bfloat162_rn(acc[mt][nt][2], acc[mt][nt][3]);
        }
    }
}

// ---------------- fp32 -> bf16 convert ----------------
__global__ __launch_bounds__(256) void cvt_k(const float* __restrict__ in,
                                             __nv_bfloat16* __restrict__ out)
{
    size_t i = ((size_t)blockIdx.x * blockDim.x + threadIdx.x) * 8;
    float4 a = *(const float4*)(in + i);
    float4 b = *(const float4*)(in + i + 4);
    __nv_bfloat162 r[4];
    r[0] = __floats2bfloat162_rn(a.x, a.y);
    r[1] = __floats2bfloat162_rn(a.z, a.w);
    r[2] = __floats2bfloat162_rn(b.x, b.y);
    r[3] = __floats2bfloat162_rn(b.z, b.w);
    *(uint4*)(out + i) = *(const uint4*)r;
}

// ---------------- transpose + convert ----------------
__global__ __launch_bounds__(256) void cvtT_k(const float* __restrict__ W,
                                              __nv_bfloat16* __restrict__ Wt)
{
    __shared__ float t[32][33];
    int x  = blockIdx.x * 32 + threadIdx.x;
    int y0 = blockIdx.y * 32;
    #pragma unroll
    for (int r = threadIdx.y; r < 32; r += 8)
        t[r][threadIdx.x] = W[(size_t)(y0 + r) * HDIM + x];
    __syncthreads();
    int xo = y0 + threadIdx.x;
    #pragma unroll
    for (int r = threadIdx.y; r < 32; r += 8)
        Wt[(size_t)(blockIdx.x * 32 + r) * HDIM + xo] = __float2bfloat16(t[threadIdx.x][r]);
}

// ---------------- LayerNorm for query ----------------
__global__ __launch_bounds__(256) void ln_q_k(
    const __nv_bfloat16* __restrict__ qpre,
    const float* __restrict__ bq, const float* __restrict__ gq,
    const float* __restrict__ betaq, float* __restrict__ qout)
{
    const int lane = threadIdx.x & 31;
    const int wid  = threadIdx.x >> 5;
    const int row  = blockIdx.x * 8 + wid;
    const size_t base = (size_t)row * HDIM;

    float x[32];
    float s = 0.f, sq = 0.f;
    #pragma unroll
    for (int i = 0; i < 16; i++) {
        int j = i * 64 + lane * 2;
        __nv_bfloat162 v = *(const __nv_bfloat162*)(qpre + base + j);
        float a = __low2float(v)  + bq[j];
        float c = __high2float(v) + bq[j + 1];
        x[2*i] = a; x[2*i+1] = c;
        s += a + c; sq += a * a + c * c;
    }
    #pragma unroll
    for (int o = 16; o > 0; o >>= 1) {
        s  += __shfl_xor_sync(0xffffffffu, s,  o);
        sq += __shfl_xor_sync(0xffffffffu, sq, o);
    }
    float mean = s * (1.f / 1024.f);
    float var  = sq * (1.f / 1024.f) - mean * mean;
    float rstd = rsqrtf(var + 1e-5f);
    #pragma unroll
    for (int i = 0; i < 16; i++) {
        int j = i * 64 + lane * 2;
        float2 o;
        o.x = (x[2*i]   - mean) * rstd * gq[j]   + betaq[j];
        o.y = (x[2*i+1] - mean) * rstd * gq[j+1] + betaq[j+1];
        *(float2*)(qout + base + j) = o;
    }
}

// ---------------- fused: keyp-LN + relu(q+keyp) . Wb -> beta ----------------
// grid (BDIM, 2): each CTA handles 32 of the 64 s-rows; 8 warps x 4 rows.
__global__ __launch_bounds__(256) void beta_k(
    const __nv_bfloat16* __restrict__ kc, const float* __restrict__ q,
    const float* __restrict__ bk, const float* __restrict__ gk,
    const float* __restrict__ betak, const float* __restrict__ Wb,
    const float* __restrict__ bb, float* __restrict__ beta)
{
    __shared__ float bks[HDIM], gks[HDIM], cqs[HDIM], wbs[HDIM];
    const int b    = blockIdx.x;
    const int half = blockIdx.y;          // 0 or 1
    const int tid  = threadIdx.x;
    const int lane = tid & 31;
    const int wid  = tid >> 5;

    for (int j = tid; j < HDIM; j += 256) {
        bks[j] = bk[j];
        gks[j] = gk[j];
        cqs[j] = betak[j] + q[(size_t)b * HDIM + j];
        wbs[j] = Wb[j];
    }
    __syncthreads();
    const float bbv = bb[0];

    for (int s = half * 32 + wid; s < half * 32 + 32; s += 8) {
        const size_t base = ((size_t)b * SDIM + s) * HDIM;
        float x[32];
        float sm = 0.f, sq = 0.f;
        #pragma unroll
        for (int it = 0; it < 4; it++) {
            int j0 = it * 256 + lane * 8;
            uint4 raw = *(const uint4*)(kc + base + j0);
            const __nv_bfloat162* v2 = (const __nv_bfloat162*)&raw;
            #pragma unroll
            for (int e = 0; e < 4; e++) {
                float a = __low2float(v2[e])  + bks[j0 + 2*e];
                float c = __high2float(v2[e]) + bks[j0 + 2*e + 1];
                x[it*8 + 2*e]     = a;
                x[it*8 + 2*e + 1] = c;
                sm += a + c; sq += a * a + c * c;
            }
        }
        #pragma unroll
        for (int o = 16; o > 0; o >>= 1) {
            sm += __shfl_xor_sync(0xffffffffu, sm, o);
            sq += __shfl_xor_sync(0xffffffffu, sq, o);
        }
        float mean = sm * (1.f / 1024.f);
        float var  = sq * (1.f / 1024.f) - mean * mean;
        float rstd = rsqrtf(var + 1e-5f);

        float acc = 0.f;
        #pragma unroll
        for (int it = 0; it < 4; it++) {
            int j0 = it * 256 + lane * 8;
            #pragma unroll
            for (int e = 0; e < 8; e++) {
                float hv = (x[it*8 + e] - mean) * rstd * gks[j0 + e] + cqs[j0 + e];
                acc += fmaxf(hv, 0.f) * wbs[j0 + e];
            }
        }
        #pragma unroll
        for (int o = 16; o > 0; o >>= 1)
            acc += __shfl_xor_sync(0xffffffffu, acc, o);

        if (lane == 0)
            beta[(size_t)b * SDIM + s] = (acc + bbv) * (1.f / 32.f);
    }
}

// ---------------- masked softmax + cumsums ----------------
__global__ void softmax_k(const float* __restrict__ beta,
                          const float* __restrict__ prev_p,
                          float* __restrict__ out)
{
    int b = blockIdx.x * blockDim.x + threadIdx.x;
    if (b >= BDIM) return;
    const float* bt = beta   + (size_t)b * SDIM;
    const float* pp = prev_p + (size_t)b * SDIM;

    float mx = -1e30f;
    #pragma unroll
    for (int s = 0; s < SDIM; s++) mx = fmaxf(mx, bt[s]);

    float pcs[SDIM];
    float run = 0.f;
    #pragma unroll
    for (int s = 0; s < SDIM; s++) { run += pp[s]; pcs[s] = run; }

    float x[SDIM];
    float denom = 0.f;
    #pragma unroll
    for (int s = 0; s < SDIM; s++) {
        float mask = (s < SDIM - 1)
                   ? ((pcs[s + 1] < 1e-5f) ? 0.f : pcs[s + 1])
                   : 1.f;
        x[s] = expf(bt[s] - mx) * mask;
        denom += fabsf(x[s]);
    }
    denom = fmaxf(denom, 1e-12f);

    const size_t BS = (size_t)BDIM * SDIM;
    float cp = 0.f;
    #pragma unroll
    for (int s = 0; s < SDIM; s++) {
        float p = x[s] / denom;
        x[s] = p;
        cp += p;
        out[0 * BS + (size_t)b * SDIM + s] = cp;
        out[2 * BS + (size_t)b * SDIM + s] = p;
    }
    float rcp = 0.f;
    #pragma unroll
    for (int s = SDIM - 1; s >= 0; s--) {
        rcp += x[s];
        out[1 * BS + (size_t)b * SDIM + s] = rcp;
    }
}

// ---------------- launch ----------------
extern "C" void kernel_launch(void* const* d_in, const int* in_sizes, int n_in,
                              void* d_out, int out_size)
{
    const float* in_val     = (const float*)d_in[0];
    const float* prev_out_M = (const float*)d_in[1];
    const float* prev_p     = (const float*)d_in[2];
    const float* Wq         = (const float*)d_in[3];
    const float* bq         = (const float*)d_in[4];
    const float* gq         = (const float*)d_in[5];
    const float* betaq      = (const float*)d_in[6];
    const float* Wk         = (const float*)d_in[7];
    const float* bk         = (const float*)d_in[8];
    const float* gk         = (const float*)d_in[9];
    const float* betak      = (const float*)d_in[10];
    const float* Wb         = (const float*)d_in[11];
    const float* bb         = (const float*)d_in[12];
    float* out = (float*)d_out;

    __nv_bfloat16 *abf, *inbf, *wqt, *wkt, *kc, *qpre;
    float *qf, *betap;
    cudaGetSymbolAddress((void**)&abf,   g_abf);
    cudaGetSymbolAddress((void**)&inbf,  g_inbf);
    cudaGetSymbolAddress((void**)&wqt,   g_wqt);
    cudaGetSymbolAddress((void**)&wkt,   g_wkt);
    cudaGetSymbolAddress((void**)&kc,    g_kc);
    cudaGetSymbolAddress((void**)&qpre,  g_qpre);
    cudaGetSymbolAddress((void**)&qf,    g_q);
    cudaGetSymbolAddress((void**)&betap, g_beta);

    cudaFuncSetAttribute(gemm_bf16_k, cudaFuncAttributeMaxDynamicSharedMemorySize, GEMM_SMEM);

    cvt_k <<<((size_t)MROWS * HDIM / 8) / 256, 256>>>(prev_out_M, abf);
    cvt_k <<<((size_t)BDIM  * HDIM / 8) / 256, 256>>>(in_val, inbf);
    cvtT_k<<<dim3(32, 32), dim3(32, 8)>>>(Wq, wqt);
    cvtT_k<<<dim3(32, 32), dim3(32, 8)>>>(Wk, wkt);

    gemm_bf16_k<<<dim3(8, BDIM  / 128), 256, GEMM_SMEM>>>(inbf, wqt, qpre);
    gemm_bf16_k<<<dim3(8, MROWS / 128), 256, GEMM_SMEM>>>(abf,  wkt, kc);

    ln_q_k   <<<BDIM / 8, 256>>>(qpre, bq, gq, betaq, qf);
    beta_k   <<<dim3(BDIM, 2), 256>>>(kc, qf, bk, gk, betak, Wb, bb, betap);
    softmax_k<<<(BDIM + 127) / 128, 128>>>(betap, prev_p, out);
}

// round 11
// speedup vs baseline: 1.5802x; 1.0462x over previous
#include <cuda_runtime.h>
#include <cuda_bf16.h>
#include <cstdint>

#define HDIM 1024
#define BDIM 2048
#define SDIM 64
#define MROWS (BDIM * SDIM)   // 131072

// ---------------- scratch ----------------
__device__ __nv_bfloat16 g_abf [(size_t)MROWS * HDIM];
__device__ __nv_bfloat16 g_inbf[(size_t)BDIM * HDIM];
__device__ __nv_bfloat16 g_wqt [(size_t)HDIM * HDIM];
__device__ __nv_bfloat16 g_wkt [(size_t)HDIM * HDIM];
__device__ __nv_bfloat16 g_kc  [(size_t)MROWS * HDIM];
__device__ __nv_bfloat16 g_qpre[(size_t)BDIM * HDIM];
__device__ float         g_q   [(size_t)BDIM * HDIM];
__device__ float         g_beta[(size_t)BDIM * SDIM];

#define CPASYNC16(sm, gm) \
    asm volatile("cp.async.cg.shared.global [%0], [%1], 16;\n" :: "r"(sm), "l"(gm))
#define CP_COMMIT() asm volatile("cp.async.commit_group;\n" ::: "memory")
#define CP_WAIT1()  asm volatile("cp.async.wait_group 1;\n" ::: "memory")
#define CP_WAIT0()  asm volatile("cp.async.wait_group 0;\n" ::: "memory")
#define LDMX4(r0, r1, r2, r3, a) \
    asm volatile("ldmatrix.sync.aligned.m8n8.x4.shared.b16 {%0,%1,%2,%3}, [%4];" \
        : "=r"(r0), "=r"(r1), "=r"(r2), "=r"(r3) : "r"(a))

__device__ __forceinline__ uint32_t smem_u32(const void* p) {
    uint32_t a;
    asm("{ .reg .u64 t; cvta.to.shared.u64 t, %1; cvt.u32.u64 %0, t; }" : "=r"(a) : "l"(p));
    return a;
}

// ================= pipelined bf16 mma.sync GEMM (R4 core, merged launch) =================
// blockIdx.y < 16  -> C0[2048,1024]   = A0 @ Bt0^T   (query GEMM)
// blockIdx.y >= 16 -> C1[131072,1024] = A1 @ Bt1^T   (key GEMM)
// CTA tile 128x128, k-chunk 64, 3-stage cp.async ring, 2 CTAs/SM,
// 8 warps (2x4), warp tile 64x32.
#define NSTG   3
#define KC     64
#define CHUNKS (HDIM / KC)              // 16
#define RSTRIDE 144
#define STG_A   (128 * RSTRIDE)
#define STG_BYTES (2 * STG_A)           // 36864
#define GEMM_SMEM (NSTG * STG_BYTES)    // 110592

#define QBLKS (BDIM / 128)              // 16

__global__ __launch_bounds__(256, 2) void gemm_bf16_k(
    const __nv_bfloat16* __restrict__ A0, const __nv_bfloat16* __restrict__ Bt0,
    __nv_bfloat16* __restrict__ C0,
    const __nv_bfloat16* __restrict__ A1, const __nv_bfloat16* __restrict__ Bt1,
    __nv_bfloat16* __restrict__ C1)
{
    extern __shared__ __align__(128) char smem[];
    const uint32_t sb = smem_u32(smem);

    const int tid   = threadIdx.x;
    const int lane  = tid & 31;
    const int wid   = tid >> 5;
    const int warpM = wid >> 2;
    const int warpN = wid & 3;

    const bool small = (blockIdx.y < QBLKS);
    const __nv_bfloat16* A  = small ? A0  : A1;
    const __nv_bfloat16* Bt = small ? Bt0 : Bt1;
    __nv_bfloat16*       C  = small ? C0  : C1;
    const size_t bm = (size_t)(small ? blockIdx.y : (blockIdx.y - QBLKS)) * 128;
    const size_t bn = (size_t)blockIdx.x * 128;

    float acc[4][4][4];
    #pragma unroll
    for (int mt = 0; mt < 4; mt++)
        #pragma unroll
        for (int nt = 0; nt < 4; nt++)
            #pragma unroll
            for (int i = 0; i < 4; i++) acc[mt][nt][i] = 0.f;

    const int prow = tid >> 3;
    const int pg   = tid & 7;
    const __nv_bfloat16* gA = A  + (bm + prow) * HDIM + pg * 8;
    const __nv_bfloat16* gB = Bt + (bn + prow) * HDIM + pg * 8;
    const uint32_t pdst = prow * RSTRIDE + pg * 16;

    const uint32_t aF = (warpM * 64 + ((lane >> 3) & 1) * 8 + (lane & 7)) * RSTRIDE
                      + ((lane >> 4) * 8) * 2;
    const uint32_t bF = STG_A
                      + (warpN * 32 + ((lane >> 4) & 1) * 8 + (lane & 7)) * RSTRIDE
                      + (((lane >> 3) & 1) * 8) * 2;

    #pragma unroll
    for (int kt = 0; kt < 2; kt++) {
        const uint32_t s = sb + kt * STG_BYTES;
        #pragma unroll
        for (int i = 0; i < 4; i++) {
            CPASYNC16(s + pdst + i * 32 * RSTRIDE,          gA + (size_t)i * 32 * HDIM + kt * KC);
            CPASYNC16(s + STG_A + pdst + i * 32 * RSTRIDE,  gB + (size_t)i * 32 * HDIM + kt * KC);
        }
        CP_COMMIT();
    }

    for (int kt = 0; kt < CHUNKS; kt++) {
        if (kt < CHUNKS - 1) CP_WAIT1(); else CP_WAIT0();
        __syncthreads();

        if (kt + 2 < CHUNKS) {
            const uint32_t s = sb + ((kt + 2) % NSTG) * STG_BYTES;
            #pragma unroll
            for (int i = 0; i < 4; i++) {
                CPASYNC16(s + pdst + i * 32 * RSTRIDE,         gA + (size_t)i * 32 * HDIM + (kt + 2) * KC);
                CPASYNC16(s + STG_A + pdst + i * 32 * RSTRIDE, gB + (size_t)i * 32 * HDIM + (kt + 2) * KC);
            }
            CP_COMMIT();
        }

        const uint32_t stg = sb + (kt % NSTG) * STG_BYTES;
        #pragma unroll
        for (int ks = 0; ks < KC; ks += 16) {
            uint32_t af[4][4];
            uint32_t bf[4][2];
            #pragma unroll
            for (int mt = 0; mt < 4; mt++)
                LDMX4(af[mt][0], af[mt][1], af[mt][2], af[mt][3],
                      stg + aF + mt * 16 * RSTRIDE + ks * 2);
            #pragma unroll
            for (int np = 0; np < 2; np++) {
                uint32_t b0, b1, b2, b3;
                LDMX4(b0, b1, b2, b3, stg + bF + np * 16 * RSTRIDE + ks * 2);
                bf[2*np][0]   = b0; bf[2*np][1]   = b1;
                bf[2*np+1][0] = b2; bf[2*np+1][1] = b3;
            }
            #pragma unroll
            for (int mt = 0; mt < 4; mt++)
                #pragma unroll
                for (int nt = 0; nt < 4; nt++)
                    asm volatile(
                        "mma.sync.aligned.m16n8k16.row.col.f32.bf16.bf16.f32 "
                        "{%0,%1,%2,%3},{%4,%5,%6,%7},{%8,%9},{%0,%1,%2,%3};\n"
                        : "+f"(acc[mt][nt][0]), "+f"(acc[mt][nt][1]),
                          "+f"(acc[mt][nt][2]), "+f"(acc[mt][nt][3])
                        : "r"(af[mt][0]), "r"(af[mt][1]), "r"(af[mt][2]), "r"(af[mt][3]),
                          "r"(bf[nt][0]), "r"(bf[nt][1]));
        }
    }

    #pragma unroll
    for (int mt = 0; mt < 4; mt++) {
        int r = warpM * 64 + mt * 16 + (lane >> 2);
        #pragma unroll
        for (int nt = 0; nt < 4; nt++) {
            size_t c  = bn + warpN * 32 + nt * 8 + (lane & 3) * 2;
            size_t b0 = (bm + r) * HDIM + c;
            *(__nv_bfloat162*)(C + b0) =
                __floats2bfloat162_rn(acc[mt][nt][0], acc[mt][nt][1]);
            *(__nv_bfloat162*)(C + b0 + (size_t)8 * HDIM) =
                __floats2bfloat162_rn(acc[mt][nt][2], acc[mt][nt][3]);
        }
    }
}

// ---------------- fp32 -> bf16 convert ----------------
__global__ __launch_bounds__(256) void cvt_k(const float* __restrict__ in,
                                             __nv_bfloat16* __restrict__ out)
{
    size_t i = ((size_t)blockIdx.x * blockDim.x + threadIdx.x) * 8;
    float4 a = *(const float4*)(in + i);
    float4 b = *(const float4*)(in + i + 4);
    __nv_bfloat162 r[4];
    r[0] = __floats2bfloat162_rn(a.x, a.y);
    r[1] = __floats2bfloat162_rn(a.z, a.w);
    r[2] = __floats2bfloat162_rn(b.x, b.y);
    r[3] = __floats2bfloat162_rn(b.z, b.w);
    *(uint4*)(out + i) = *(const uint4*)r;
}

// ---------------- transpose + convert ----------------
__global__ __launch_bounds__(256) void cvtT_k(const float* __restrict__ W,
                                              __nv_bfloat16* __restrict__ Wt)
{
    __shared__ float t[32][33];
    int x  = blockIdx.x * 32 + threadIdx.x;
    int y0 = blockIdx.y * 32;
    #pragma unroll
    for (int r = threadIdx.y; r < 32; r += 8)
        t[r][threadIdx.x] = W[(size_t)(y0 + r) * HDIM + x];
    __syncthreads();
    int xo = y0 + threadIdx.x;
    #pragma unroll
    for (int r = threadIdx.y; r < 32; r += 8)
        Wt[(size_t)(blockIdx.x * 32 + r) * HDIM + xo] = __float2bfloat16(t[threadIdx.x][r]);
}

// ---------------- LayerNorm for query ----------------
__global__ __launch_bounds__(256) void ln_q_k(
    const __nv_bfloat16* __restrict__ qpre,
    const float* __restrict__ bq, const float* __restrict__ gq,
    const float* __restrict__ betaq, float* __restrict__ qout)
{
    const int lane = threadIdx.x & 31;
    const int wid  = threadIdx.x >> 5;
    const int row  = blockIdx.x * 8 + wid;
    const size_t base = (size_t)row * HDIM;

    float x[32];
    float s = 0.f, sq = 0.f;
    #pragma unroll
    for (int i = 0; i < 16; i++) {
        int j = i * 64 + lane * 2;
        __nv_bfloat162 v = *(const __nv_bfloat162*)(qpre + base + j);
        float a = __low2float(v)  + bq[j];
        float c = __high2float(v) + bq[j + 1];
        x[2*i] = a; x[2*i+1] = c;
        s += a + c; sq += a * a + c * c;
    }
    #pragma unroll
    for (int o = 16; o > 0; o >>= 1) {
        s  += __shfl_xor_sync(0xffffffffu, s,  o);
        sq += __shfl_xor_sync(0xffffffffu, sq, o);
    }
    float mean = s * (1.f / 1024.f);
    float var  = sq * (1.f / 1024.f) - mean * mean;
    float rstd = rsqrtf(var + 1e-5f);
    #pragma unroll
    for (int i = 0; i < 16; i++) {
        int j = i * 64 + lane * 2;
        float2 o;
        o.x = (x[2*i]   - mean) * rstd * gq[j]   + betaq[j];
        o.y = (x[2*i+1] - mean) * rstd * gq[j+1] + betaq[j+1];
        *(float2*)(qout + base + j) = o;
    }
}

// ---------------- fused: keyp-LN + relu(q+keyp) . Wb -> beta ----------------
// 1 CTA per batch, 8 warps x 8 rows. Each warp streams its rows through a
// per-warp cp.async double buffer (2 x 2KB) to hide DRAM latency.
__global__ __launch_bounds__(256) void beta_k(
    const __nv_bfloat16* __restrict__ kc, const float* __restrict__ q,
    const float* __restrict__ bk, const float* __restrict__ gk,
    const float* __restrict__ betak, const float* __restrict__ Wb,
    const float* __restrict__ bb, float* __restrict__ beta)
{
    __shared__ float bks[HDIM], gks[HDIM], cqs[HDIM], wbs[HDIM];
    extern __shared__ __align__(16) __nv_bfloat16 rowbuf[];   // [8 warps][2][1024]

    const int b    = blockIdx.x;
    const int tid  = threadIdx.x;
    const int lane = tid & 31;
    const int wid  = tid >> 5;

    for (int j = tid; j < HDIM; j += 256) {
        bks[j] = bk[j];
        gks[j] = gk[j];
        cqs[j] = betak[j] + q[(size_t)b * HDIM + j];
        wbs[j] = Wb[j];
    }
    __syncthreads();
    const float bbv = bb[0];

    __nv_bfloat16* mybuf = rowbuf + wid * 2 * HDIM;
    const uint32_t buf_s = smem_u32(mybuf);
    const __nv_bfloat16* gbase = kc + ((size_t)b * SDIM) * HDIM;

    // prefetch first row (s = wid) into buf 0: 32 lanes x 4 x 16B
    {
        const __nv_bfloat16* src = gbase + (size_t)wid * HDIM;
        #pragma unroll
        for (int qd = 0; qd < 4; qd++)
            CPASYNC16(buf_s + qd * 512 + lane * 16, src + qd * 256 + lane * 8);
        CP_COMMIT();
    }

    #pragma unroll
    for (int i = 0; i < 8; i++) {
        const int s = wid + i * 8;
        // prefetch next row into the other buffer
        if (i < 7) {
            const __nv_bfloat16* src = gbase + (size_t)(s + 8) * HDIM;
            const uint32_t d = buf_s + ((i + 1) & 1) * (HDIM * 2);
            #pragma unroll
            for (int qd = 0; qd < 4; qd++)
                CPASYNC16(d + qd * 512 + lane * 16, src + qd * 256 + lane * 8);
            CP_COMMIT();
            CP_WAIT1();
        } else {
            CP_WAIT0();
        }
        __syncwarp();

        const __nv_bfloat16* rb = mybuf + (i & 1) * HDIM;
        float x[32];
        float sm = 0.f, sq = 0.f;
        #pragma unroll
        for (int it = 0; it < 4; it++) {
            int j0 = it * 256 + lane * 8;
            uint4 raw = *(const uint4*)(rb + j0);
            const __nv_bfloat162* v2 = (const __nv_bfloat162*)&raw;
            #pragma unroll
            for (int e = 0; e < 4; e++) {
                float a = __low2float(v2[e])  + bks[j0 + 2*e];
                float c = __high2float(v2[e]) + bks[j0 + 2*e + 1];
                x[it*8 + 2*e]     = a;
                x[it*8 + 2*e + 1] = c;
                sm += a + c; sq += a * a + c * c;
            }
        }
        __syncwarp();
        #pragma unroll
        for (int o = 16; o > 0; o >>= 1) {
            sm += __shfl_xor_sync(0xffffffffu, sm, o);
            sq += __shfl_xor_sync(0xffffffffu, sq, o);
        }
        float mean = sm * (1.f / 1024.f);
        float var  = sq * (1.f / 1024.f) - mean * mean;
        float rstd = rsqrtf(var + 1e-5f);

        float acc = 0.f;
        #pragma unroll
        for (int it = 0; it < 4; it++) {
            int j0 = it * 256 + lane * 8;
            #pragma unroll
            for (int e = 0; e < 8; e++) {
                float hv = (x[it*8 + e] - mean) * rstd * gks[j0 + e] + cqs[j0 + e];
                acc += fmaxf(hv, 0.f) * wbs[j0 + e];
            }
        }
        #pragma unroll
        for (int o = 16; o > 0; o >>= 1)
            acc += __shfl_xor_sync(0xffffffffu, acc, o);

        if (lane == 0)
            beta[(size_t)b * SDIM + s] = (acc + bbv) * (1.f / 32.f);
    }
}
#define BETA_DYN_SMEM (8 * 2 * HDIM * 2)   // 32768 B

// ---------------- masked softmax + cumsums ----------------
__global__ void softmax_k(const float* __restrict__ beta,
                          const float* __restrict__ prev_p,
                          float* __restrict__ out)
{
    int b = blockIdx.x * blockDim.x + threadIdx.x;
    if (b >= BDIM) return;
    const float* bt = beta   + (size_t)b * SDIM;
    const float* pp = prev_p + (size_t)b * SDIM;

    float mx = -1e30f;
    #pragma unroll
    for (int s = 0; s < SDIM; s++) mx = fmaxf(mx, bt[s]);

    float pcs[SDIM];
    float run = 0.f;
    #pragma unroll
    for (int s = 0; s < SDIM; s++) { run += pp[s]; pcs[s] = run; }

    float x[SDIM];
    float denom = 0.f;
    #pragma unroll
    for (int s = 0; s < SDIM; s++) {
        float mask = (s < SDIM - 1)
                   ? ((pcs[s + 1] < 1e-5f) ? 0.f : pcs[s + 1])
                   : 1.f;
        x[s] = expf(bt[s] - mx) * mask;
        denom += fabsf(x[s]);
    }
    denom = fmaxf(denom, 1e-12f);

    const size_t BS = (size_t)BDIM * SDIM;
    float cp = 0.f;
    #pragma unroll
    for (int s = 0; s < SDIM; s++) {
        float p = x[s] / denom;
        x[s] = p;
        cp += p;
        out[0 * BS + (size_t)b * SDIM + s] = cp;
        out[2 * BS + (size_t)b * SDIM + s] = p;
    }
    float rcp = 0.f;
    #pragma unroll
    for (int s = SDIM - 1; s >= 0; s--) {
        rcp += x[s];
        out[1 * BS + (size_t)b * SDIM + s] = rcp;
    }
}

// ---------------- launch ----------------
extern "C" void kernel_launch(void* const* d_in, const int* in_sizes, int n_in,
                              void* d_out, int out_size)
{
    const float* in_val     = (const float*)d_in[0];
    const float* prev_out_M = (const float*)d_in[1];
    const float* prev_p     = (const float*)d_in[2];
    const float* Wq         = (const float*)d_in[3];
    const float* bq         = (const float*)d_in[4];
    const float* gq         = (const float*)d_in[5];
    const float* betaq      = (const float*)d_in[6];
    const float* Wk         = (const float*)d_in[7];
    const float* bk         = (const float*)d_in[8];
    const float* gk         = (const float*)d_in[9];
    const float* betak      = (const float*)d_in[10];
    const float* Wb         = (const float*)d_in[11];
    const float* bb         = (const float*)d_in[12];
    float* out = (float*)d_out;

    __nv_bfloat16 *abf, *inbf, *wqt, *wkt, *kc, *qpre;
    float *qf, *betap;
    cudaGetSymbolAddress((void**)&abf,   g_abf);
    cudaGetSymbolAddress((void**)&inbf,  g_inbf);
    cudaGetSymbolAddress((void**)&wqt,   g_wqt);
    cudaGetSymbolAddress((void**)&wkt,   g_wkt);
    cudaGetSymbolAddress((void**)&kc,    g_kc);
    cudaGetSymbolAddress((void**)&qpre,  g_qpre);
    cudaGetSymbolAddress((void**)&qf,    g_q);
    cudaGetSymbolAddress((void**)&betap, g_beta);

    cudaFuncSetAttribute(gemm_bf16_k, cudaFuncAttributeMaxDynamicSharedMemorySize, GEMM_SMEM);

    cvt_k <<<((size_t)MROWS * HDIM / 8) / 256, 256>>>(prev_out_M, abf);
    cvt_k <<<((size_t)BDIM  * HDIM / 8) / 256, 256>>>(in_val, inbf);
    cvtT_k<<<dim3(32, 32), dim3(32, 8)>>>(Wq, wqt);
    cvtT_k<<<dim3(32, 32), dim3(32, 8)>>>(Wk, wkt);

    // merged GEMM: y<16 -> query GEMM, else key GEMM
    gemm_bf16_k<<<dim3(8, QBLKS + MROWS / 128), 256, GEMM_SMEM>>>(
        inbf, wqt, qpre, abf, wkt, kc);

    ln_q_k   <<<BDIM / 8, 256>>>(qpre, bq, gq, betaq, qf);
    beta_k   <<<BDIM, 256, BETA_DYN_SMEM>>>(kc, qf, bk, gk, betak, Wb, bb, betap);
    softmax_k<<<(BDIM + 127) / 128, 128>>>(betap, prev_p, out);
}